// round 11
// baseline (speedup 1.0000x reference)
#include <cuda_runtime.h>
#include <cstdint>

#define NTH 128               // 4 warps
#define RPW 32                // output rows per warp
#define STAGES 4              // cp.async ring depth (rows in flight per warp)

__device__ __forceinline__ void cp_async16(uint32_t saddr, const void* gptr) {
    asm volatile("cp.async.cg.shared.global [%0], [%1], 16;\n"
                 :: "r"(saddr), "l"(gptr) : "memory");
}
__device__ __forceinline__ void cp_commit() {
    asm volatile("cp.async.commit_group;\n" ::: "memory");
}
template <int N>
__device__ __forceinline__ void cp_wait() {
    asm volatile("cp.async.wait_group %0;\n" :: "n"(N) : "memory");
}

__global__ __launch_bounds__(NTH, 12)
void conv3x3_v11(const float* __restrict__ X,
                 const float* __restrict__ Kp,
                 float* __restrict__ O,
                 int H, int W)
{
    // warp-private ring: [warp][stage][256 floats] (1KB per row)
    __shared__ float buf[4][STAGES][256];

    const int bc = blockIdx.z;
    const float* __restrict__ Xp = X + (size_t)bc * H * W;
    float* __restrict__ Op       = O + (size_t)bc * H * W;

    const float k00 = __ldg(&Kp[0]), k01 = __ldg(&Kp[1]), k02 = __ldg(&Kp[2]);
    const float k10 = __ldg(&Kp[3]), k11 = __ldg(&Kp[4]), k12 = __ldg(&Kp[5]);
    const float k20 = __ldg(&Kp[6]), k21 = __ldg(&Kp[7]), k22 = __ldg(&Kp[8]);

    const int tid  = threadIdx.x;
    const int warp = tid >> 5;
    const int lane = tid & 31;
    const int y0   = blockIdx.y * (4 * RPW) + warp * RPW;

    const int W4g = W >> 2;   // 64
    float4* __restrict__ Op4 = (float4*)Op;
    const float4 Z = make_float4(0.f, 0.f, 0.f, 0.f);

    float* wbase = &buf[warp][0][0];
    const uint32_t sbase = (uint32_t)__cvta_generic_to_shared(wbase) + lane * 16u;

    // issue row t into stage s; always commits exactly one group
    auto issue_row = [&](int t, int s, bool valid) {
        if (valid && t >= 0 && t < H) {
            const float* g = Xp + (size_t)t * W + lane * 4;
            const uint32_t a = sbase + (uint32_t)s * 1024u;
            cp_async16(a,        g);
            cp_async16(a + 512u, g + 128);
        } else if (valid) {
            float4* d = (float4*)(wbase + s * 256 + lane * 4);
            d[0]  = Z;
            d[32] = Z;
        }
        cp_commit();
    };

    // prologue: rows y0-1 .. y0+2 into stages 0..3
    #pragma unroll
    for (int s = 0; s < STAGES; s++)
        issue_row(y0 - 1 + s, s, true);

    float4 pLo = Z, pHi = Z;   // out row t-1 (awaiting kernel row 2)
    float4 qLo = Z, qHi = Z;   // out row t+1 partial (kernel row 0)

    #pragma unroll 2
    for (int i = 0; i <= RPW + 1; i++) {
        const int t = y0 - 1 + i;
        const int s = i & (STAGES - 1);

        cp_wait<STAGES - 1>();   // oldest group (stage s) complete

        // read this lane's own bytes back (no cross-thread smem reads -> no sync)
        const float4* src = (const float4*)(wbase + s * 256 + lane * 4);
        const float4 vLo = src[0];
        const float4 vHi = src[32];

        // refill stage s with row t+STAGES (only if it will be consumed)
        issue_row(t + STAGES, s, (i + STAGES) <= RPW + 1);

        // horizontal neighbors: unconditional shuffles + value selects
        const float upLo = __shfl_up_sync(0xffffffffu,   vLo.w, 1);
        const float dnLo = __shfl_down_sync(0xffffffffu, vLo.x, 1);
        const float upHi = __shfl_up_sync(0xffffffffu,   vHi.w, 1);
        const float dnHi = __shfl_down_sync(0xffffffffu, vHi.x, 1);
        const float crossL = __shfl_sync(0xffffffffu, vLo.w, 31);
        const float crossR = __shfl_sync(0xffffffffu, vHi.x, 0);

        const float Llo = (lane == 0)  ? 0.f    : upLo;
        const float Rlo = (lane == 31) ? crossR : dnLo;
        const float Lhi = (lane == 0)  ? crossL : upHi;
        const float Rhi = (lane == 31) ? 0.f    : dnHi;

        // out row t-1 completes with kernel row 2 of input row t
        pLo.x += k20 * Llo   + k21 * vLo.x + k22 * vLo.y;
        pLo.y += k20 * vLo.x + k21 * vLo.y + k22 * vLo.z;
        pLo.z += k20 * vLo.y + k21 * vLo.z + k22 * vLo.w;
        pLo.w += k20 * vLo.z + k21 * vLo.w + k22 * Rlo;
        pHi.x += k20 * Lhi   + k21 * vHi.x + k22 * vHi.y;
        pHi.y += k20 * vHi.x + k21 * vHi.y + k22 * vHi.z;
        pHi.z += k20 * vHi.y + k21 * vHi.z + k22 * vHi.w;
        pHi.w += k20 * vHi.z + k21 * vHi.w + k22 * Rhi;
        if (i >= 2) {
            const size_t rb = (size_t)(t - 1) * W4g;
            Op4[rb + lane]      = pLo;
            Op4[rb + lane + 32] = pHi;
        }

        // out row t: previous partial + kernel row 1
        pLo.x = qLo.x + (k10 * Llo   + k11 * vLo.x + k12 * vLo.y);
        pLo.y = qLo.y + (k10 * vLo.x + k11 * vLo.y + k12 * vLo.z);
        pLo.z = qLo.z + (k10 * vLo.y + k11 * vLo.z + k12 * vLo.w);
        pLo.w = qLo.w + (k10 * vLo.z + k11 * vLo.w + k12 * Rlo);
        pHi.x = qHi.x + (k10 * Lhi   + k11 * vHi.x + k12 * vHi.y);
        pHi.y = qHi.y + (k10 * vHi.x + k11 * vHi.y + k12 * vHi.z);
        pHi.z = qHi.z + (k10 * vHi.y + k11 * vHi.z + k12 * vHi.w);
        pHi.w = qHi.w + (k10 * vHi.z + k11 * vHi.w + k12 * Rhi);

        // out row t+1: kernel row 0
        qLo.x = k00 * Llo   + k01 * vLo.x + k02 * vLo.y;
        qLo.y = k00 * vLo.x + k01 * vLo.y + k02 * vLo.z;
        qLo.z = k00 * vLo.y + k01 * vLo.z + k02 * vLo.w;
        qLo.w = k00 * vLo.z + k01 * vLo.w + k02 * Rlo;
        qHi.x = k00 * Lhi   + k01 * vHi.x + k02 * vHi.y;
        qHi.y = k00 * vHi.x + k01 * vHi.y + k02 * vHi.z;
        qHi.z = k00 * vHi.y + k01 * vHi.z + k02 * vHi.w;
        qHi.w = k00 * vHi.z + k01 * vHi.w + k02 * Rhi;
    }
}

extern "C" void kernel_launch(void* const* d_in, const int* in_sizes, int n_in,
                              void* d_out, int out_size)
{
    const float* X = (const float*)d_in[0];   // (16, 64, 256, 256) fp32
    const float* K = (const float*)d_in[1];   // (3, 3) fp32
    float* O = (float*)d_out;

    const int H = 256, W = 256;
    const int planes = in_sizes[0] / (H * W); // 1024

    dim3 block(NTH, 1, 1);
    dim3 grid(1, H / (4 * RPW), planes);      // (1, 2, 1024) = 2048 blocks
    conv3x3_v11<<<grid, block>>>(X, K, O, H, W);
}

// round 12
// speedup vs baseline: 1.2110x; 1.2110x over previous
#include <cuda_runtime.h>
#include <cstdint>

#define NTH 128               // 4 warps
#define RPW 32                // output rows per warp
#define STAGES 5              // cp.async ring depth (issue-ahead = 4 rows)

__device__ __forceinline__ void cp_async16(uint32_t saddr, const void* gptr) {
    asm volatile("cp.async.cg.shared.global [%0], [%1], 16;\n"
                 :: "r"(saddr), "l"(gptr) : "memory");
}
__device__ __forceinline__ void cp_commit() {
    asm volatile("cp.async.commit_group;\n" ::: "memory");
}
template <int N>
__device__ __forceinline__ void cp_wait() {
    asm volatile("cp.async.wait_group %0;\n" :: "n"(N) : "memory");
}

__global__ __launch_bounds__(NTH)
void conv3x3_v12(const float* __restrict__ X,
                 const float* __restrict__ Kp,
                 float* __restrict__ O,
                 int H, int W)
{
    // warp-private ring: [warp][stage][256 floats] (1KB per row)
    __shared__ float buf[4][STAGES][256];

    const int bc = blockIdx.z;
    const float* __restrict__ Xp = X + (size_t)bc * H * W;
    float* __restrict__ Op       = O + (size_t)bc * H * W;

    const float k00 = __ldg(&Kp[0]), k01 = __ldg(&Kp[1]), k02 = __ldg(&Kp[2]);
    const float k10 = __ldg(&Kp[3]), k11 = __ldg(&Kp[4]), k12 = __ldg(&Kp[5]);
    const float k20 = __ldg(&Kp[6]), k21 = __ldg(&Kp[7]), k22 = __ldg(&Kp[8]);

    const int tid  = threadIdx.x;
    const int warp = tid >> 5;
    const int lane = tid & 31;
    const int y0   = blockIdx.y * (4 * RPW) + warp * RPW;

    const int W4g = W >> 2;   // 64
    float4* __restrict__ Op4 = (float4*)Op;
    const float4 Z = make_float4(0.f, 0.f, 0.f, 0.f);

    float* wbase = &buf[warp][0][0];
    const uint32_t sbase = (uint32_t)__cvta_generic_to_shared(wbase) + lane * 16u;

    // issue row t into stage s; always commits exactly one group
    auto issue_row = [&](int t, int s, bool valid) {
        if (valid && t >= 0 && t < H) {
            const float* g = Xp + (size_t)t * W + lane * 4;
            const uint32_t a = sbase + (uint32_t)s * 1024u;
            cp_async16(a,        g);
            cp_async16(a + 512u, g + 128);
        } else if (valid) {
            float4* d = (float4*)(wbase + s * 256 + lane * 4);
            d[0]  = Z;
            d[32] = Z;
        }
        cp_commit();
    };

    // prologue: rows y0-1 .. y0+STAGES-2 into stages 0..STAGES-1
    #pragma unroll
    for (int s = 0; s < STAGES; s++)
        issue_row(y0 - 1 + s, s, true);

    float4 pLo = Z, pHi = Z;   // out row t-1 (awaiting kernel row 2)
    float4 qLo = Z, qHi = Z;   // out row t+1 partial (kernel row 0)

    int s = 0;
    #pragma unroll 2
    for (int i = 0; i <= RPW + 1; i++) {
        const int t = y0 - 1 + i;

        cp_wait<STAGES - 1>();   // oldest group (stage s) complete

        // read this lane's own bytes back (no cross-thread smem reads -> no sync)
        const float4* src = (const float4*)(wbase + s * 256 + lane * 4);
        const float4 vLo = src[0];
        const float4 vHi = src[32];

        // refill stage s with row t+STAGES (only if it will be consumed)
        issue_row(t + STAGES, s, (i + STAGES) <= RPW + 1);
        s = (s == STAGES - 1) ? 0 : s + 1;

        // horizontal neighbors: unconditional shuffles + value selects
        const float upLo = __shfl_up_sync(0xffffffffu,   vLo.w, 1);
        const float dnLo = __shfl_down_sync(0xffffffffu, vLo.x, 1);
        const float upHi = __shfl_up_sync(0xffffffffu,   vHi.w, 1);
        const float dnHi = __shfl_down_sync(0xffffffffu, vHi.x, 1);
        const float crossL = __shfl_sync(0xffffffffu, vLo.w, 31);
        const float crossR = __shfl_sync(0xffffffffu, vHi.x, 0);

        const float Llo = (lane == 0)  ? 0.f    : upLo;
        const float Rlo = (lane == 31) ? crossR : dnLo;
        const float Lhi = (lane == 0)  ? crossL : upHi;
        const float Rhi = (lane == 31) ? 0.f    : dnHi;

        // out row t-1 completes with kernel row 2 of input row t
        pLo.x += k20 * Llo   + k21 * vLo.x + k22 * vLo.y;
        pLo.y += k20 * vLo.x + k21 * vLo.y + k22 * vLo.z;
        pLo.z += k20 * vLo.y + k21 * vLo.z + k22 * vLo.w;
        pLo.w += k20 * vLo.z + k21 * vLo.w + k22 * Rlo;
        pHi.x += k20 * Lhi   + k21 * vHi.x + k22 * vHi.y;
        pHi.y += k20 * vHi.x + k21 * vHi.y + k22 * vHi.z;
        pHi.z += k20 * vHi.y + k21 * vHi.z + k22 * vHi.w;
        pHi.w += k20 * vHi.z + k21 * vHi.w + k22 * Rhi;
        if (i >= 2) {
            const size_t rb = (size_t)(t - 1) * W4g;
            Op4[rb + lane]      = pLo;
            Op4[rb + lane + 32] = pHi;
        }

        // out row t: previous partial + kernel row 1
        pLo.x = qLo.x + (k10 * Llo   + k11 * vLo.x + k12 * vLo.y);
        pLo.y = qLo.y + (k10 * vLo.x + k11 * vLo.y + k12 * vLo.z);
        pLo.z = qLo.z + (k10 * vLo.y + k11 * vLo.z + k12 * vLo.w);
        pLo.w = qLo.w + (k10 * vLo.z + k11 * vLo.w + k12 * Rlo);
        pHi.x = qHi.x + (k10 * Lhi   + k11 * vHi.x + k12 * vHi.y);
        pHi.y = qHi.y + (k10 * vHi.x + k11 * vHi.y + k12 * vHi.z);
        pHi.z = qHi.z + (k10 * vHi.y + k11 * vHi.z + k12 * vHi.w);
        pHi.w = qHi.w + (k10 * vHi.z + k11 * vHi.w + k12 * Rhi);

        // out row t+1: kernel row 0
        qLo.x = k00 * Llo   + k01 * vLo.x + k02 * vLo.y;
        qLo.y = k00 * vLo.x + k01 * vLo.y + k02 * vLo.z;
        qLo.z = k00 * vLo.y + k01 * vLo.z + k02 * vLo.w;
        qLo.w = k00 * vLo.z + k01 * vLo.w + k02 * Rlo;
        qHi.x = k00 * Lhi   + k01 * vHi.x + k02 * vHi.y;
        qHi.y = k00 * vHi.x + k01 * vHi.y + k02 * vHi.z;
        qHi.z = k00 * vHi.y + k01 * vHi.z + k02 * vHi.w;
        qHi.w = k00 * vHi.z + k01 * vHi.w + k02 * Rhi;
    }
}

extern "C" void kernel_launch(void* const* d_in, const int* in_sizes, int n_in,
                              void* d_out, int out_size)
{
    const float* X = (const float*)d_in[0];   // (16, 64, 256, 256) fp32
    const float* K = (const float*)d_in[1];   // (3, 3) fp32
    float* O = (float*)d_out;

    const int H = 256, W = 256;
    const int planes = in_sizes[0] / (H * W); // 1024

    dim3 block(NTH, 1, 1);
    dim3 grid(1, H / (4 * RPW), planes);      // (1, 2, 1024) = 2048 blocks
    conv3x3_v12<<<grid, block>>>(X, K, O, H, W);
}